// round 6
// baseline (speedup 1.0000x reference)
#include <cuda_runtime.h>
#include <cuda_bf16.h>
#include <cstdint>

// ---------------------------------------------------------------------------
// ScaleSelfAttention: out = x + gamma * softmax((xWf)(xWg)^T) (xWh)
// B=4, N=4096, C=256, d=32
//   proj_kernel : f,g fp32 transposed; h bf16 transposed; ||f||^2; per-block
//                 max ||g||^2. Inner loop on packed fma.rn.f32x2.
//   attn_kernel : 64 q/CTA. S fp32 via f32x2 FFMA, P = exp(S - mhat) with
//                 mhat = ||f||*max||g|| (upper bound -> single pass, no
//                 rescale). O += P.H via mma.sync bf16, fragments via
//                 ldmatrix.x4. Epilogue fuses x + gamma*O/l.
// ---------------------------------------------------------------------------

#define BATCH 4
#define NTOK  4096
#define CDIM  256
#define DDIM  32

__device__ float         g_ft[BATCH * DDIM * NTOK];
__device__ float         g_gt[BATCH * DDIM * NTOK];
__device__ __nv_bfloat16 g_ht[BATCH * CDIM * NTOK];
__device__ float         g_fn2[BATCH * NTOK];
__device__ float         g_g2blk[256];          // per-proj-block max ||g||^2

typedef unsigned long long ull;

__device__ __forceinline__ void fma2(ull& d, ull a, ull b) {
    asm("fma.rn.f32x2 %0, %1, %2, %0;" : "+l"(d) : "l"(a), "l"(b));
}
__device__ __forceinline__ ull splat2(float v) {
    ull r;
    asm("mov.b64 %0, {%1, %1};" : "=l"(r) : "f"(v));
    return r;
}
__device__ __forceinline__ float2 unpack2(ull v) {
    float2 r;
    asm("mov.b64 {%0, %1}, %2;" : "=f"(r.x), "=f"(r.y) : "l"(v));
    return r;
}

// ---------------------------------------------------------------------------
// Projections: [16384 x 256] @ [256 x 320], 64 rows/block, K chunked by 64.
// ---------------------------------------------------------------------------
__global__ __launch_bounds__(256) void proj_kernel(
    const float* __restrict__ x,
    const float* __restrict__ wf,
    const float* __restrict__ wg,
    const float* __restrict__ wh)
{
    __shared__ float sX[64 * 65];
    __shared__ float sW[64 * 64];
    __shared__ float sGm[2];

    const int t = threadIdx.x;
    const int rowBase = blockIdx.x * 64;
    const int bb = rowBase >> 12;
    const int tokBase = rowBase & 4095;
    const int rg = t >> 4;
    const int cg = t & 15;

    ull acc[5][8];   // [cc][i*2 + jpair]
#pragma unroll
    for (int cc = 0; cc < 5; cc++)
#pragma unroll
        for (int q = 0; q < 8; q++) acc[cc][q] = 0ull;

    for (int kc = 0; kc < 4; kc++) {
        __syncthreads();
        for (int idx = t; idx < 4096; idx += 256) {
            int r = idx >> 6, kk = idx & 63;
            sX[r * 65 + kk] = x[(rowBase + r) * 256 + kc * 64 + kk];
        }
#pragma unroll
        for (int cc = 0; cc < 5; cc++) {
            __syncthreads();
            for (int idx = t; idx < 4096; idx += 256) {
                int kk = idx >> 6, j = idx & 63;
                int kglob = kc * 64 + kk;
                int c = cc * 64 + j;
                float w;
                if (c < 32)       w = wf[kglob * 32 + c];
                else if (c < 64)  w = wg[kglob * 32 + (c - 32)];
                else              w = wh[kglob * 256 + (c - 64)];
                sW[kk * 64 + j] = w;
            }
            __syncthreads();
#pragma unroll 4
            for (int kk = 0; kk < 64; kk++) {
                ulonglong2 bp = *(const ulonglong2*)&sW[kk * 64 + cg * 4];
                ull as[4];
#pragma unroll
                for (int i = 0; i < 4; i++)
                    as[i] = splat2(sX[(rg * 4 + i) * 65 + kk]);
#pragma unroll
                for (int i = 0; i < 4; i++) {
                    fma2(acc[cc][i * 2 + 0], as[i], bp.x);
                    fma2(acc[cc][i * 2 + 1], as[i], bp.y);
                }
            }
        }
    }

#pragma unroll
    for (int cc = 0; cc < 5; cc++) {
        __syncthreads();
#pragma unroll
        for (int i = 0; i < 4; i++) {
            float2 lo = unpack2(acc[cc][i * 2 + 0]);
            float2 hi = unpack2(acc[cc][i * 2 + 1]);
            sX[(rg * 4 + i) * 65 + cg * 4 + 0] = lo.x;
            sX[(rg * 4 + i) * 65 + cg * 4 + 1] = lo.y;
            sX[(rg * 4 + i) * 65 + cg * 4 + 2] = hi.x;
            sX[(rg * 4 + i) * 65 + cg * 4 + 3] = hi.y;
        }
        __syncthreads();

        if (cc == 0) {
            float g2 = 0.f;
            if (t < 64) {
                float f2 = 0.f;
#pragma unroll 8
                for (int k = 0; k < 32; k++) {
                    float v = sX[t * 65 + k];      f2 += v * v;
                    float w = sX[t * 65 + 32 + k]; g2 += w * w;
                }
                g_fn2[rowBase + t] = f2;
            }
            if (t < 64) {
#pragma unroll
                for (int o = 16; o > 0; o >>= 1)
                    g2 = fmaxf(g2, __shfl_xor_sync(0xffffffffu, g2, o));
                if ((t & 31) == 0) sGm[t >> 5] = g2;
            }
            for (int idx = t; idx < 4096; idx += 256) {
                int c = idx >> 6, tok = idx & 63;
                float v = sX[tok * 65 + c];
                if (c < 32) g_ft[(bb * 32 + c) * 4096 + tokBase + tok] = v;
                else        g_gt[(bb * 32 + (c - 32)) * 4096 + tokBase + tok] = v;
            }
        } else {
            for (int idx = t; idx < 4096; idx += 256) {
                int c = idx >> 6, tok = idx & 63;
                float v = sX[tok * 65 + c];
                g_ht[(size_t)(bb * 256 + (cc - 1) * 64 + c) * 4096 + tokBase + tok] =
                    __float2bfloat16(v);
            }
        }
    }
    __syncthreads();
    if (t == 0) g_g2blk[blockIdx.x] = fmaxf(sGm[0], sGm[1]);
}

// ---------------------------------------------------------------------------
// Attention kernel: mma.sync bf16 + ldmatrix, f32x2 S phase
// ---------------------------------------------------------------------------
#define HS_STRIDE 176
#define PB_STRIDE 176
#define FT_STRIDE 68
#define HS_OFF 0
#define PB_OFF (256 * HS_STRIDE)
#define FT_OFF (PB_OFF + 64 * PB_STRIDE)
#define GT_OFF (FT_OFF + 32 * FT_STRIDE * 4)
#define GT_BUF (32 * FT_STRIDE * 4)
#define SL_OFF (GT_OFF + 2 * GT_BUF)
#define SR_OFF (SL_OFF + 256)
#define SM_BYTES (SR_OFF + 64)

__device__ __forceinline__ uint32_t smem_u32(const void* p) {
    uint32_t a;
    asm("{ .reg .u64 t; cvta.to.shared.u64 t, %1; cvt.u32.u64 %0, t; }"
        : "=r"(a) : "l"(p));
    return a;
}
__device__ __forceinline__ void cp_async16(uint32_t dst, const void* src) {
    asm volatile("cp.async.cg.shared.global [%0], [%1], 16;"
                 :: "r"(dst), "l"(src) : "memory");
}
__device__ __forceinline__ void mma16816(float* d, const uint32_t* a,
                                         const uint32_t* bv) {
    asm volatile(
        "mma.sync.aligned.m16n8k16.row.col.f32.bf16.bf16.f32 "
        "{%0,%1,%2,%3}, {%4,%5,%6,%7}, {%8,%9}, {%0,%1,%2,%3};"
        : "+f"(d[0]), "+f"(d[1]), "+f"(d[2]), "+f"(d[3])
        : "r"(a[0]), "r"(a[1]), "r"(a[2]), "r"(a[3]), "r"(bv[0]), "r"(bv[1]));
}
#define LDMX4(r0, r1, r2, r3, addr) \
    asm volatile("ldmatrix.sync.aligned.m8n8.x4.shared.b16 {%0,%1,%2,%3}, [%4];" \
                 : "=r"(r0), "=r"(r1), "=r"(r2), "=r"(r3) : "r"(addr))

__global__ __launch_bounds__(256, 2) void attn_kernel(
    const float* __restrict__ x,
    const float* __restrict__ gamma_p,
    float* __restrict__ out)
{
    extern __shared__ char sm[];
    const int t = threadIdx.x;
    const int lane = t & 31;
    const int wid = t >> 5;
    const int gid = lane >> 2;
    const int tig = lane & 3;
    const int b = blockIdx.y;
    const int qBase = blockIdx.x * 64;
    const int rgA = t >> 4;
    const int cgA = t & 15;

    float* sFt = (float*)(sm + FT_OFF);
    float* sL  = (float*)(sm + SL_OFF);
    float* sR  = (float*)(sm + SR_OFF);
    const uint32_t smbase = smem_u32(sm);

    // prologue: F^T, G^T tile 0, l init, batch gmax reduce
    for (int idx = t; idx < 2048; idx += 256) {
        int k = idx >> 6, tok = idx & 63;
        sFt[k * FT_STRIDE + tok] = g_ft[(b * 32 + k) * 4096 + qBase + tok];
        ((float*)(sm + GT_OFF))[k * FT_STRIDE + tok] =
            g_gt[(b * 32 + k) * 4096 + tok];
    }
    if (t < 64) sL[t] = 0.f;
    {
        float gv = g_g2blk[b * 64 + (t & 63)];
#pragma unroll
        for (int o = 16; o > 0; o >>= 1)
            gv = fmaxf(gv, __shfl_xor_sync(0xffffffffu, gv, o));
        if (lane == 0) sR[wid] = gv;
    }
    __syncthreads();

    float gm2 = sR[0];
#pragma unroll
    for (int w = 1; w < 8; w++) gm2 = fmaxf(gm2, sR[w]);
    const float gms = sqrtf(gm2);
    float mh[4];
#pragma unroll
    for (int i = 0; i < 4; i++)
        mh[i] = sqrtf(g_fn2[b * 4096 + qBase + rgA * 4 + i]) * gms;

    float acc[16][4];
#pragma unroll
    for (int j = 0; j < 16; j++)
#pragma unroll
        for (int q = 0; q < 4; q++) acc[j][q] = 0.f;

    const int qoff = (wid & 3) * 16;
    const int coff = (wid >> 2) * 128;

    // ldmatrix lane addresses
    const uint32_t aLdm = smbase + PB_OFF +
        (qoff + ((lane & 15) >> 3) * 8 + (lane & 7)) * PB_STRIDE +
        ((lane >> 4) << 4);
    const uint32_t bLdm = smbase + HS_OFF +
        (coff + (lane & 7)) * HS_STRIDE + ((lane >> 3) << 4);

    for (int kt = 0; kt < 64; kt++) {
        __syncthreads();

        // async fill H^T tile [256 c][64 key] bf16
#pragma unroll
        for (int it = 0; it < 8; it++) {
            int idx = t + it * 256;
            int ch = idx >> 3, part = idx & 7;
            uint32_t dst = smbase + HS_OFF + ch * HS_STRIDE + part * 16;
            const __nv_bfloat16* src =
                g_ht + (size_t)(b * 256 + ch) * 4096 + kt * 64 + part * 8;
            cp_async16(dst, src);
        }
        if (kt < 63) {
#pragma unroll
            for (int it = 0; it < 2; it++) {
                int idx = t + it * 256;
                int k = idx >> 4, chunk = idx & 15;
                uint32_t dst = smbase + GT_OFF + ((kt + 1) & 1) * GT_BUF +
                               k * (FT_STRIDE * 4) + chunk * 16;
                const float* src =
                    g_gt + (size_t)(b * 32 + k) * 4096 + (kt + 1) * 64 + chunk * 4;
                cp_async16(dst, src);
            }
        }
        asm volatile("cp.async.commit_group;" ::: "memory");

        // ---- S = F.G^T via f32x2 ; P = exp(S - mhat) ----
        const float* sG = (const float*)(sm + GT_OFF + (kt & 1) * GT_BUF);
        ull pA[2][4];
#pragma unroll
        for (int ip = 0; ip < 2; ip++)
#pragma unroll
            for (int j = 0; j < 4; j++) pA[ip][j] = 0ull;

#pragma unroll 8
        for (int kk = 0; kk < 32; kk++) {
            ulonglong2 fp = *(const ulonglong2*)&sFt[kk * FT_STRIDE + rgA * 4];
            float4 g4 = *(const float4*)&sG[kk * FT_STRIDE + cgA * 4];
            ull gs0 = splat2(g4.x), gs1 = splat2(g4.y);
            ull gs2 = splat2(g4.z), gs3 = splat2(g4.w);
            fma2(pA[0][0], fp.x, gs0); fma2(pA[1][0], fp.y, gs0);
            fma2(pA[0][1], fp.x, gs1); fma2(pA[1][1], fp.y, gs1);
            fma2(pA[0][2], fp.x, gs2); fma2(pA[1][2], fp.y, gs2);
            fma2(pA[0][3], fp.x, gs3); fma2(pA[1][3], fp.y, gs3);
        }

        float p[4][4];
#pragma unroll
        for (int ip = 0; ip < 2; ip++)
#pragma unroll
            for (int j = 0; j < 4; j++) {
                float2 v = unpack2(pA[ip][j]);
                p[2 * ip][j] = v.x;
                p[2 * ip + 1][j] = v.y;
            }

        float rs[4];
#pragma unroll
        for (int i = 0; i < 4; i++) {
            p[i][0] = __expf(p[i][0] - mh[i]);
            p[i][1] = __expf(p[i][1] - mh[i]);
            p[i][2] = __expf(p[i][2] - mh[i]);
            p[i][3] = __expf(p[i][3] - mh[i]);
            rs[i] = (p[i][0] + p[i][1]) + (p[i][2] + p[i][3]);
        }
#pragma unroll
        for (int off = 1; off < 16; off <<= 1)
#pragma unroll
            for (int i = 0; i < 4; i++)
                rs[i] += __shfl_xor_sync(0xffffffffu, rs[i], off);
        if (cgA == 0) {
#pragma unroll
            for (int i = 0; i < 4; i++) sL[rgA * 4 + i] += rs[i];
        }

        // store P bf16 [64 q][64 key]
#pragma unroll
        for (int i = 0; i < 4; i++) {
            __nv_bfloat162 lo = __floats2bfloat162_rn(p[i][0], p[i][1]);
            __nv_bfloat162 hi = __floats2bfloat162_rn(p[i][2], p[i][3]);
            uint2 v;
            v.x = *(uint32_t*)&lo;
            v.y = *(uint32_t*)&hi;
            *(uint2*)(sm + PB_OFF + (rgA * 4 + i) * PB_STRIDE + cgA * 8) = v;
        }

        asm volatile("cp.async.wait_group 0;" ::: "memory");
        __syncthreads();

        // ---- MMA: warp slab 16q x 128c, 64 keys; ldmatrix fragments ----
        uint32_t a[4][4];
#pragma unroll
        for (int s = 0; s < 4; s++)
            LDMX4(a[s][0], a[s][1], a[s][2], a[s][3], aLdm + 32 * s);

#pragma unroll
        for (int j = 0; j < 16; j++) {
            uint32_t b0[4], b1[4];
            uint32_t bj = bLdm + j * (8 * HS_STRIDE);
            LDMX4(b0[0], b0[1], b0[2], b0[3], bj);
            LDMX4(b1[0], b1[1], b1[2], b1[3], bj + 64);
            mma16816(acc[j], a[0], &b0[0]);
            mma16816(acc[j], a[1], &b0[2]);
            mma16816(acc[j], a[2], &b1[0]);
            mma16816(acc[j], a[3], &b1[2]);
        }
    }
    __syncthreads();

    // ---- epilogue: out = x + gamma * O / l ----
    const float gamma = *gamma_p;
    const int r0 = qoff + gid;
    const int r1 = r0 + 8;
    const float gl0 = gamma / sL[r0];
    const float gl1 = gamma / sL[r1];
    const size_t gb0 = (size_t)(b * NTOK + qBase + r0) * CDIM + coff + tig * 2;
    const size_t gb1 = (size_t)(b * NTOK + qBase + r1) * CDIM + coff + tig * 2;

#pragma unroll
    for (int j = 0; j < 16; j++) {
        float2 xv0 = *(const float2*)&x[gb0 + j * 8];
        float2 xv1 = *(const float2*)&x[gb1 + j * 8];
        float2 o0, o1;
        o0.x = xv0.x + gl0 * acc[j][0];
        o0.y = xv0.y + gl0 * acc[j][1];
        o1.x = xv1.x + gl1 * acc[j][2];
        o1.y = xv1.y + gl1 * acc[j][3];
        *(float2*)&out[gb0 + j * 8] = o0;
        *(float2*)&out[gb1 + j * 8] = o1;
    }
}

// ---------------------------------------------------------------------------
extern "C" void kernel_launch(void* const* d_in, const int* in_sizes, int n_in,
                              void* d_out, int out_size)
{
    const float* x  = (const float*)d_in[0];
    const float* wf = (const float*)d_in[1];
    const float* wg = (const float*)d_in[2];
    const float* wh = (const float*)d_in[3];
    const float* gm = (const float*)d_in[4];
    float* out = (float*)d_out;

    cudaFuncSetAttribute(attn_kernel,
                         cudaFuncAttributeMaxDynamicSharedMemorySize,
                         SM_BYTES);

    proj_kernel<<<256, 256>>>(x, wf, wg, wh);
    attn_kernel<<<dim3(64, 4), 256, SM_BYTES>>>(x, gm, out);
}

// round 7
// speedup vs baseline: 1.2551x; 1.2551x over previous
#include <cuda_runtime.h>
#include <cuda_bf16.h>
#include <cstdint>

// ---------------------------------------------------------------------------
// ScaleSelfAttention: out = x + gamma * softmax((xWf)(xWg)^T) (xWh)
// B=4, N=4096, C=256, d=32
//  proj_kernel: h bf16 transposed [b][c][tok]; f,g as bf16 hi/lo split
//               extended operands (K=96): f_ext=[hi|hi|lo], g_ext=[hi|lo|hi]
//               so S = f.g exactly to ~1e-4 abs via 3 bf16 MMA terms.
//               Also ||f||^2 and per-block max ||g||^2.
//  attn_kernel: 64 q/CTA. S via mma.sync bf16 (K=96) from ldmatrix frags,
//               P = exp(S - mhat), mhat = ||f||*max||g|| (upper bound ->
//               single pass, no rescale). O += P.H via mma.sync bf16.
//               Row sums in registers (deterministic). Epilogue fuses
//               x + gamma*O/l.
// ---------------------------------------------------------------------------

#define BATCH 4
#define NTOK  4096
#define CDIM  256
#define DDIM  32

__device__ __nv_bfloat16 g_fe[BATCH * NTOK * 96];   // f extended
__device__ __nv_bfloat16 g_ge[BATCH * NTOK * 96];   // g extended
__device__ __nv_bfloat16 g_ht[BATCH * CDIM * NTOK]; // h transposed
__device__ float         g_fn2[BATCH * NTOK];
__device__ float         g_g2blk[256];

typedef unsigned long long ull;

__device__ __forceinline__ void fma2(ull& d, ull a, ull b) {
    asm("fma.rn.f32x2 %0, %1, %2, %0;" : "+l"(d) : "l"(a), "l"(b));
}
__device__ __forceinline__ ull splat2(float v) {
    ull r;
    asm("mov.b64 %0, {%1, %1};" : "=l"(r) : "f"(v));
    return r;
}
__device__ __forceinline__ float2 unpack2(ull v) {
    float2 r;
    asm("mov.b64 {%0, %1}, %2;" : "=f"(r.x), "=f"(r.y) : "l"(v));
    return r;
}
__device__ __forceinline__ uint32_t pack_bf2(float a, float b) {
    __nv_bfloat162 v = __floats2bfloat162_rn(a, b);
    return *(uint32_t*)&v;
}

// ---------------------------------------------------------------------------
// Projections
// ---------------------------------------------------------------------------
__global__ __launch_bounds__(256) void proj_kernel(
    const float* __restrict__ x,
    const float* __restrict__ wf,
    const float* __restrict__ wg,
    const float* __restrict__ wh)
{
    __shared__ float sX[64 * 65];
    __shared__ float sW[64 * 64];
    __shared__ float sGm[2];

    const int t = threadIdx.x;
    const int rowBase = blockIdx.x * 64;
    const int bb = rowBase >> 12;
    const int tokBase = rowBase & 4095;
    const int rg = t >> 4;
    const int cg = t & 15;

    ull acc[5][8];
#pragma unroll
    for (int cc = 0; cc < 5; cc++)
#pragma unroll
        for (int q = 0; q < 8; q++) acc[cc][q] = 0ull;

    for (int kc = 0; kc < 4; kc++) {
        __syncthreads();
        for (int idx = t; idx < 4096; idx += 256) {
            int r = idx >> 6, kk = idx & 63;
            sX[r * 65 + kk] = x[(rowBase + r) * 256 + kc * 64 + kk];
        }
#pragma unroll
        for (int cc = 0; cc < 5; cc++) {
            __syncthreads();
            for (int idx = t; idx < 4096; idx += 256) {
                int kk = idx >> 6, j = idx & 63;
                int kglob = kc * 64 + kk;
                int c = cc * 64 + j;
                float w;
                if (c < 32)       w = wf[kglob * 32 + c];
                else if (c < 64)  w = wg[kglob * 32 + (c - 32)];
                else              w = wh[kglob * 256 + (c - 64)];
                sW[kk * 64 + j] = w;
            }
            __syncthreads();
#pragma unroll 4
            for (int kk = 0; kk < 64; kk++) {
                ulonglong2 bp = *(const ulonglong2*)&sW[kk * 64 + cg * 4];
                ull as[4];
#pragma unroll
                for (int i = 0; i < 4; i++)
                    as[i] = splat2(sX[(rg * 4 + i) * 65 + kk]);
#pragma unroll
                for (int i = 0; i < 4; i++) {
                    fma2(acc[cc][i * 2 + 0], as[i], bp.x);
                    fma2(acc[cc][i * 2 + 1], as[i], bp.y);
                }
            }
        }
    }

#pragma unroll
    for (int cc = 0; cc < 5; cc++) {
        __syncthreads();
#pragma unroll
        for (int i = 0; i < 4; i++) {
            float2 lo = unpack2(acc[cc][i * 2 + 0]);
            float2 hi = unpack2(acc[cc][i * 2 + 1]);
            sX[(rg * 4 + i) * 65 + cg * 4 + 0] = lo.x;
            sX[(rg * 4 + i) * 65 + cg * 4 + 1] = lo.y;
            sX[(rg * 4 + i) * 65 + cg * 4 + 2] = hi.x;
            sX[(rg * 4 + i) * 65 + cg * 4 + 3] = hi.y;
        }
        __syncthreads();

        if (cc == 0) {
            float g2 = 0.f;
            if (t < 64) {
                float f2 = 0.f;
#pragma unroll 8
                for (int k = 0; k < 32; k++) {
                    float v = sX[t * 65 + k];      f2 += v * v;
                    float w = sX[t * 65 + 32 + k]; g2 += w * w;
                }
                g_fn2[rowBase + t] = f2;
#pragma unroll
                for (int o = 16; o > 0; o >>= 1)
                    g2 = fmaxf(g2, __shfl_xor_sync(0xffffffffu, g2, o));
                if ((t & 31) == 0) sGm[t >> 5] = g2;
            }
            // extended bf16 split operands: pairs of columns
            for (int idx = t; idx < 64 * 48; idx += 256) {
                int tok = idx / 48;
                int c0 = (idx % 48) * 2;
                size_t grow = (size_t)(bb * 4096 + tokBase + tok) * 96 + c0;
                // f_ext: cols 0-63 = hi(f[c&31]), 64-95 = lo(f[c-64])
                {
                    int jf = (c0 < 64) ? (c0 & 31) : (c0 - 64);
                    float f0 = sX[tok * 65 + jf];
                    float f1 = sX[tok * 65 + jf + 1];
                    __nv_bfloat16 h0 = __float2bfloat16(f0);
                    __nv_bfloat16 h1 = __float2bfloat16(f1);
                    uint32_t w;
                    if (c0 < 64) {
                        __nv_bfloat162 v2 = {h0, h1};
                        w = *(uint32_t*)&v2;
                    } else {
                        w = pack_bf2(f0 - __bfloat162float(h0),
                                     f1 - __bfloat162float(h1));
                    }
                    *(uint32_t*)&g_fe[grow] = w;
                }
                // g_ext: cols 0-31 = hi(g[c]), 32-63 = lo(g[c-32]), 64-95 = hi(g[c-64])
                {
                    int jg = (c0 < 32) ? c0 : ((c0 < 64) ? (c0 - 32) : (c0 - 64));
                    float ga = sX[tok * 65 + 32 + jg];
                    float gb = sX[tok * 65 + 32 + jg + 1];
                    __nv_bfloat16 h0 = __float2bfloat16(ga);
                    __nv_bfloat16 h1 = __float2bfloat16(gb);
                    uint32_t w;
                    if (c0 < 32 || c0 >= 64) {
                        __nv_bfloat162 v2 = {h0, h1};
                        w = *(uint32_t*)&v2;
                    } else {
                        w = pack_bf2(ga - __bfloat162float(h0),
                                     gb - __bfloat162float(h1));
                    }
                    *(uint32_t*)&g_ge[grow] = w;
                }
            }
        } else {
            for (int idx = t; idx < 4096; idx += 256) {
                int c = idx >> 6, tok = idx & 63;
                float v = sX[tok * 65 + c];
                g_ht[(size_t)(bb * 256 + (cc - 1) * 64 + c) * 4096 + tokBase + tok] =
                    __float2bfloat16(v);
            }
        }
    }
    __syncthreads();
    if (t == 0) g_g2blk[blockIdx.x] = fmaxf(sGm[0], sGm[1]);
}

// ---------------------------------------------------------------------------
// Attention kernel: tensor-core S (bf16 split) + tensor-core O
// ---------------------------------------------------------------------------
#define HS_STRIDE 176
#define PB_STRIDE 176
#define FE_STRIDE 208                     // 13*16B: ldmatrix conflict-free
#define HS_OFF 0
#define PB_OFF (256 * HS_STRIDE)          // 45056
#define FE_OFF (PB_OFF + 64 * PB_STRIDE)  // 56320
#define GE_OFF (FE_OFF + 64 * FE_STRIDE)  // 69632
#define GE_BUF (64 * FE_STRIDE)           // 13312
#define SLP_OFF (GE_OFF + 2 * GE_BUF)     // 96256
#define SR_OFF (SLP_OFF + 512)            // 96768
#define SM_BYTES (SR_OFF + 32)            // 96800

__device__ __forceinline__ uint32_t smem_u32(const void* p) {
    uint32_t a;
    asm("{ .reg .u64 t; cvta.to.shared.u64 t, %1; cvt.u32.u64 %0, t; }"
        : "=r"(a) : "l"(p));
    return a;
}
__device__ __forceinline__ void cp_async16(uint32_t dst, const void* src) {
    asm volatile("cp.async.cg.shared.global [%0], [%1], 16;"
                 :: "r"(dst), "l"(src) : "memory");
}
__device__ __forceinline__ void mma16816(float* d, const uint32_t* a,
                                         const uint32_t* bv) {
    asm volatile(
        "mma.sync.aligned.m16n8k16.row.col.f32.bf16.bf16.f32 "
        "{%0,%1,%2,%3}, {%4,%5,%6,%7}, {%8,%9}, {%0,%1,%2,%3};"
        : "+f"(d[0]), "+f"(d[1]), "+f"(d[2]), "+f"(d[3])
        : "r"(a[0]), "r"(a[1]), "r"(a[2]), "r"(a[3]), "r"(bv[0]), "r"(bv[1]));
}
#define LDMX4(r0, r1, r2, r3, addr) \
    asm volatile("ldmatrix.sync.aligned.m8n8.x4.shared.b16 {%0,%1,%2,%3}, [%4];" \
                 : "=r"(r0), "=r"(r1), "=r"(r2), "=r"(r3) : "r"(addr))

__global__ __launch_bounds__(256, 2) void attn_kernel(
    const float* __restrict__ x,
    const float* __restrict__ gamma_p,
    float* __restrict__ out)
{
    extern __shared__ char sm[];
    const int t = threadIdx.x;
    const int lane = t & 31;
    const int wid = t >> 5;
    const int gid = lane >> 2;
    const int tig = lane & 3;
    const int b = blockIdx.y;
    const int qBase = blockIdx.x * 64;
    const int qw = wid & 3;       // 16-query slab
    const int kw = wid >> 2;      // S: 32-key half ; O: 128-col half

    float* sLp = (float*)(sm + SLP_OFF);   // [2][64] partial row sums
    float* sR  = (float*)(sm + SR_OFF);
    const uint32_t smbase = smem_u32(sm);

    const int r0 = qw * 16 + gid;
    const int r1 = r0 + 8;

    // ---- prologue: F_ext (once) + G_ext tile 0 ----
    for (int i = t; i < 768; i += 256) {
        int row = i / 12, ch = i % 12;
        cp_async16(smbase + FE_OFF + row * FE_STRIDE + ch * 16,
                   g_fe + (size_t)(b * 4096 + qBase + row) * 96 + ch * 8);
        cp_async16(smbase + GE_OFF + row * FE_STRIDE + ch * 16,
                   g_ge + (size_t)(b * 4096 + row) * 96 + ch * 8);
    }
    asm volatile("cp.async.commit_group;" ::: "memory");

    {
        float gv = g_g2blk[b * 64 + (t & 63)];
#pragma unroll
        for (int o = 16; o > 0; o >>= 1)
            gv = fmaxf(gv, __shfl_xor_sync(0xffffffffu, gv, o));
        if (lane == 0) sR[wid] = gv;
    }
    asm volatile("cp.async.wait_group 0;" ::: "memory");
    __syncthreads();

    float gm2 = sR[0];
#pragma unroll
    for (int w = 1; w < 8; w++) gm2 = fmaxf(gm2, sR[w]);
    const float gms = sqrtf(gm2);
    const float mh0 = sqrtf(g_fn2[b * 4096 + qBase + r0]) * gms;
    const float mh1 = sqrtf(g_fn2[b * 4096 + qBase + r1]) * gms;

    float acc[16][4];
#pragma unroll
    for (int j = 0; j < 16; j++)
#pragma unroll
        for (int q = 0; q < 4; q++) acc[j][q] = 0.f;

    float rsum0 = 0.f, rsum1 = 0.f;

    const int qoff = qw * 16;
    const int coff = kw * 128;

    // ldmatrix lane addresses
    const uint32_t aS = smbase + FE_OFF + (qoff + (lane & 15)) * FE_STRIDE +
                        ((lane >> 4) << 4);
    const uint32_t bSb = smbase + GE_OFF + (kw * 32 + (lane & 7)) * FE_STRIDE +
                         ((lane >> 3) << 4);
    const uint32_t aLdm = smbase + PB_OFF + (qoff + (lane & 15)) * PB_STRIDE +
                          ((lane >> 4) << 4);
    const uint32_t bLdm = smbase + HS_OFF + (coff + (lane & 7)) * HS_STRIDE +
                          ((lane >> 3) << 4);

    for (int kt = 0; kt < 64; kt++) {
        __syncthreads();   // prev O-MMA done with HS/PB

        // async: H tile (kt) + G_ext tile (kt+1)
#pragma unroll
        for (int it = 0; it < 8; it++) {
            int idx = t + it * 256;
            int ch = idx >> 3, part = idx & 7;
            cp_async16(smbase + HS_OFF + ch * HS_STRIDE + part * 16,
                       g_ht + (size_t)(b * 256 + ch) * 4096 + kt * 64 + part * 8);
        }
        if (kt < 63) {
#pragma unroll
            for (int it = 0; it < 3; it++) {
                int i = t + it * 256;
                int row = i / 12, ch = i % 12;
                cp_async16(smbase + GE_OFF + (((kt + 1) & 1) ? GE_BUF : 0) +
                               row * FE_STRIDE + ch * 16,
                           g_ge + (size_t)(b * 4096 + (kt + 1) * 64 + row) * 96 + ch * 8);
            }
        }
        asm volatile("cp.async.commit_group;" ::: "memory");

        // ---- S-MMA: m16 x n32 x k96 per warp ----
        const uint32_t bS = bSb + ((kt & 1) ? GE_BUF : 0);
        float sacc[4][4];
#pragma unroll
        for (int nb = 0; nb < 4; nb++)
#pragma unroll
            for (int q = 0; q < 4; q++) sacc[nb][q] = 0.f;

#pragma unroll
        for (int cp = 0; cp < 3; cp++) {       // three k32 chunks
            uint32_t af[8];
            LDMX4(af[0], af[1], af[2], af[3], aS + cp * 64);
            LDMX4(af[4], af[5], af[6], af[7], aS + cp * 64 + 32);
#pragma unroll
            for (int nb = 0; nb < 4; nb++) {
                uint32_t bf[4];
                LDMX4(bf[0], bf[1], bf[2], bf[3],
                      bS + nb * 8 * FE_STRIDE + cp * 64);
                mma16816(sacc[nb], &af[0], &bf[0]);
                mma16816(sacc[nb], &af[4], &bf[2]);
            }
        }

        // ---- P = exp(S - mhat), store bf16, row-sum accumulate ----
        float rs0 = 0.f, rs1 = 0.f;
#pragma unroll
        for (int nb = 0; nb < 4; nb++) {
            float p0 = __expf(sacc[nb][0] - mh0);
            float p1 = __expf(sacc[nb][1] - mh0);
            float p2 = __expf(sacc[nb][2] - mh1);
            float p3 = __expf(sacc[nb][3] - mh1);
            rs0 += p0 + p1;
            rs1 += p2 + p3;
            int col = kw * 32 + nb * 8 + tig * 2;
            *(uint32_t*)(sm + PB_OFF + r0 * PB_STRIDE + col * 2) = pack_bf2(p0, p1);
            *(uint32_t*)(sm + PB_OFF + r1 * PB_STRIDE + col * 2) = pack_bf2(p2, p3);
        }
        rs0 += __shfl_xor_sync(0xffffffffu, rs0, 1);
        rs0 += __shfl_xor_sync(0xffffffffu, rs0, 2);
        rs1 += __shfl_xor_sync(0xffffffffu, rs1, 1);
        rs1 += __shfl_xor_sync(0xffffffffu, rs1, 2);
        rsum0 += rs0;
        rsum1 += rs1;

        asm volatile("cp.async.wait_group 0;" ::: "memory");
        __syncthreads();   // P + H (+ next G) visible

        // ---- O-MMA: warp slab 16q x 128c, 64 keys ----
        uint32_t a[4][4];
#pragma unroll
        for (int s = 0; s < 4; s++)
            LDMX4(a[s][0], a[s][1], a[s][2], a[s][3], aLdm + 32 * s);

#pragma unroll
        for (int j = 0; j < 16; j++) {
            uint32_t b0[4], b1[4];
            uint32_t bj = bLdm + j * (8 * HS_STRIDE);
            LDMX4(b0[0], b0[1], b0[2], b0[3], bj);
            LDMX4(b1[0], b1[1], b1[2], b1[3], bj + 64);
            mma16816(acc[j], a[0], &b0[0]);
            mma16816(acc[j], a[1], &b0[2]);
            mma16816(acc[j], a[2], &b1[0]);
            mma16816(acc[j], a[3], &b1[2]);
        }
    }

    // ---- final row sums (deterministic; two k-halves) ----
    if (tig == 0) {
        sLp[kw * 64 + r0] = rsum0;
        sLp[kw * 64 + r1] = rsum1;
    }
    __syncthreads();

    // ---- epilogue: out = x + gamma * O / l ----
    const float gamma = *gamma_p;
    const float gl0 = gamma / (sLp[r0] + sLp[64 + r0]);
    const float gl1 = gamma / (sLp[r1] + sLp[64 + r1]);
    const size_t gb0 = (size_t)(b * NTOK + qBase + r0) * CDIM + coff + tig * 2;
    const size_t gb1 = (size_t)(b * NTOK + qBase + r1) * CDIM + coff + tig * 2;

#pragma unroll
    for (int j = 0; j < 16; j++) {
        float2 xv0 = *(const float2*)&x[gb0 + j * 8];
        float2 xv1 = *(const float2*)&x[gb1 + j * 8];
        float2 o0, o1;
        o0.x = xv0.x + gl0 * acc[j][0];
        o0.y = xv0.y + gl0 * acc[j][1];
        o1.x = xv1.x + gl1 * acc[j][2];
        o1.y = xv1.y + gl1 * acc[j][3];
        *(float2*)&out[gb0 + j * 8] = o0;
        *(float2*)&out[gb1 + j * 8] = o1;
    }
}

// ---------------------------------------------------------------------------
extern "C" void kernel_launch(void* const* d_in, const int* in_sizes, int n_in,
                              void* d_out, int out_size)
{
    const float* x  = (const float*)d_in[0];
    const float* wf = (const float*)d_in[1];
    const float* wg = (const float*)d_in[2];
    const float* wh = (const float*)d_in[3];
    const float* gm = (const float*)d_in[4];
    float* out = (float*)d_out;

    cudaFuncSetAttribute(attn_kernel,
                         cudaFuncAttributeMaxDynamicSharedMemorySize,
                         SM_BYTES);

    proj_kernel<<<256, 256>>>(x, wf, wg, wh);
    attn_kernel<<<dim3(64, 4), 256, SM_BYTES>>>(x, gm, out);
}